// round 8
// baseline (speedup 1.0000x reference)
#include <cuda_runtime.h>
#include <cuda_fp16.h>
#include <math.h>

#define B_ 2
#define S_ 2048
#define D_ 1024
#define H_ 16
#define DK_ 64
#define NORM_ 0.125f
#define NT_ (S_ / 64)

// Scratch (allocation-free rule: device globals)
__device__ __half g_q16[(size_t)B_ * S_ * D_];
__device__ __half g_k16[(size_t)B_ * S_ * D_];
__device__ __half g_v16[(size_t)B_ * S_ * D_];
__device__ __half g_wq16[(size_t)D_ * D_];
__device__ __half g_wk16[(size_t)D_ * D_];
__device__ __half g_wv16[(size_t)D_ * D_];
__device__ __half g_wo16[(size_t)D_ * D_];
__device__ __half g_Qh[(size_t)B_ * S_ * D_];
__device__ __half g_Kh[(size_t)B_ * S_ * D_];
__device__ __half g_Vh[(size_t)B_ * S_ * D_];
__device__ __half g_ctxh[(size_t)B_ * S_ * D_];
// Permuted masks, fragment order, fp16: [b][wt(128)][kt(32)][chunk(16)][lane(32)] half2
__device__ __half2 g_pm0h[(size_t)B_ * 128 * 32 * 512];
__device__ __half2 g_pm1h[(size_t)B_ * 128 * 32 * 512];

__device__ __forceinline__ void mma_f16(float c[4], const unsigned a[4], const unsigned b0, const unsigned b1) {
    asm volatile(
        "mma.sync.aligned.m16n8k16.row.col.f32.f16.f16.f32 "
        "{%0,%1,%2,%3}, {%4,%5,%6,%7}, {%8,%9}, {%0,%1,%2,%3};"
        : "+f"(c[0]), "+f"(c[1]), "+f"(c[2]), "+f"(c[3])
        : "r"(a[0]), "r"(a[1]), "r"(a[2]), "r"(a[3]), "r"(b0), "r"(b1));
}
__device__ __forceinline__ void ldsm_x4(unsigned d[4], unsigned addr) {
    asm volatile("ldmatrix.sync.aligned.m8n8.x4.shared.b16 {%0,%1,%2,%3}, [%4];"
                 : "=r"(d[0]), "=r"(d[1]), "=r"(d[2]), "=r"(d[3]) : "r"(addr));
}
__device__ __forceinline__ void ldsm_x4_t(unsigned d[4], unsigned addr) {
    asm volatile("ldmatrix.sync.aligned.m8n8.x4.trans.shared.b16 {%0,%1,%2,%3}, [%4];"
                 : "=r"(d[0]), "=r"(d[1]), "=r"(d[2]), "=r"(d[3]) : "r"(addr));
}
__device__ __forceinline__ void cp_async16(unsigned smem_dst, const void* gsrc) {
    asm volatile("cp.async.cg.shared.global [%0], [%1], 16;" :: "r"(smem_dst), "l"(gsrc));
}
__device__ __forceinline__ void cp_commit() { asm volatile("cp.async.commit_group;"); }
__device__ __forceinline__ void cp_wait0()  { asm volatile("cp.async.wait_group 0;"); }
__device__ __forceinline__ void cp_wait1()  { asm volatile("cp.async.wait_group 1;"); }
__device__ __forceinline__ unsigned h2u(__half2 h) { return *(unsigned*)&h; }

// ---------------------------------------------------------------------------
// Fused pre-pass: convert 7 tensors fp32 -> fp16 in ONE launch.
// ---------------------------------------------------------------------------
__global__ __launch_bounds__(256)
void f2h_multi_kernel(const float* __restrict__ q, const float* __restrict__ k,
                      const float* __restrict__ v, const float* __restrict__ wq,
                      const float* __restrict__ wk, const float* __restrict__ wv,
                      const float* __restrict__ wo,
                      __half* dq, __half* dk, __half* dv,
                      __half* dwq, __half* dwk, __half* dwv, __half* dwo)
{
    int bx = blockIdx.x;
    const float* src; __half* dst; int base;
    if      (bx < 2048) { src = q;  dst = dq;  base = bx; }
    else if (bx < 4096) { src = k;  dst = dk;  base = bx - 2048; }
    else if (bx < 6144) { src = v;  dst = dv;  base = bx - 4096; }
    else if (bx < 6656) { src = wq; dst = dwq; base = bx - 6144; }
    else if (bx < 7168) { src = wk; dst = dwk; base = bx - 6656; }
    else if (bx < 7680) { src = wv; dst = dwv; base = bx - 7168; }
    else                { src = wo; dst = dwo; base = bx - 7680; }
    int i = (base * 256 + threadIdx.x) * 8;
    float4 a = *(const float4*)&src[i];
    float4 b = *(const float4*)&src[i + 4];
    uint4 o;
    o.x = h2u(__floats2half2_rn(a.x, a.y));
    o.y = h2u(__floats2half2_rn(a.z, a.w));
    o.z = h2u(__floats2half2_rn(b.x, b.y));
    o.w = h2u(__floats2half2_rn(b.z, b.w));
    *(uint4*)&dst[i] = o;
}

// ---------------------------------------------------------------------------
// Pre-pass: permute both masks into fragment order, fp16.
// ---------------------------------------------------------------------------
__global__ __launch_bounds__(512)
void permute_masks_kernel(const float* __restrict__ m0, const float* __restrict__ m1,
                          __half2* __restrict__ pm0, __half2* __restrict__ pm1)
{
    const int kt = blockIdx.x, wt = blockIdx.y, b = blockIdx.z;
    const int c = threadIdx.x >> 5, l = threadIdx.x & 31;
    const int rq = l >> 2, cq = l & 3;
    const int row = wt * 16 + rq + ((c >= 8) ? 8 : 0);
    const int col = kt * 64 + (c & 7) * 8 + cq * 2;
    const size_t soff = ((size_t)b * S_ + row) * S_ + col;
    const size_t doff = (((size_t)(b * 128 + wt)) * 32 + kt) * 512 + c * 32 + l;
    float2 a = *(const float2*)&m0[soff];
    float2 bb = *(const float2*)&m1[soff];
    pm0[doff] = __floats2half2_rn(a.x, a.y);
    pm1[doff] = __floats2half2_rn(bb.x, bb.y);
}

// ---------------------------------------------------------------------------
// fp16 GEMM core, cp.async 2-stage, K-tile 64 (unchanged from R7)
// ---------------------------------------------------------------------------
#define GST_ (128 * 72)
#define GEMM_SMEM_BYTES (4 * GST_ * 2)

__device__ __forceinline__
void gemm_core(const __half* __restrict__ A, const __half* __restrict__ W,
               const float* __restrict__ bias, void* __restrict__ Cout,
               int M, int N, int K, int half_out, __half* gsm)
{
    __half* As = gsm;
    __half* Bs = gsm + 2 * GST_;

    const int tid = threadIdx.x;
    const int lane = tid & 31;
    const int wid = tid >> 5;
    const int mbase = (wid & 3) << 5;
    const int nbase = (wid >> 2) << 6;
    const int m0 = blockIdx.y << 7;
    const int n0 = blockIdx.x << 7;

    const unsigned as_u = (unsigned)__cvta_generic_to_shared(As);
    const unsigned bs_u = (unsigned)__cvta_generic_to_shared(Bs);
    const unsigned a_loff = ((((lane >> 3) & 1) * 8 + (lane & 7)) * 72 + ((lane >> 4) & 1) * 8) * 2;
    const unsigned b_loff = ((((lane >> 4) & 1) * 8 + (lane & 7)) * 72 + ((lane >> 3) & 1) * 8) * 2;

    const int srow = tid >> 3;
    const int sc8 = (tid & 7) << 3;

    float acc[2][8][4] = {};
    const int NK = K / 64;

    {
#pragma unroll
        for (int i = 0; i < 4; i++) {
            int row = srow + i * 32;
            cp_async16(as_u + (row * 72 + sc8) * 2, A + (size_t)(m0 + row) * K + sc8);
            cp_async16(bs_u + (row * 72 + sc8) * 2, W + (size_t)(n0 + row) * K + sc8);
        }
        cp_commit();
    }

    for (int kk = 0; kk < NK; kk++) {
        const int buf = kk & 1;
        __syncthreads();
        if (kk + 1 < NK) {
            const int k0 = (kk + 1) << 6;
            unsigned off = (unsigned)((buf ^ 1) * GST_ * 2);
#pragma unroll
            for (int i = 0; i < 4; i++) {
                int row = srow + i * 32;
                cp_async16(as_u + off + (row * 72 + sc8) * 2, A + (size_t)(m0 + row) * K + k0 + sc8);
                cp_async16(bs_u + off + (row * 72 + sc8) * 2, W + (size_t)(n0 + row) * K + k0 + sc8);
            }
        }
        cp_commit();
        cp_wait1();
        __syncthreads();

        const unsigned abase = as_u + (unsigned)(buf * GST_ * 2);
        const unsigned bbase = bs_u + (unsigned)(buf * GST_ * 2);
#pragma unroll
        for (int t = 0; t < 4; t++) {
            unsigned af[2][4];
#pragma unroll
            for (int mt = 0; mt < 2; mt++)
                ldsm_x4(af[mt], abase + ((mbase + (mt << 4)) * 72 + (t << 4)) * 2 + a_loff);
#pragma unroll
            for (int a = 0; a < 8; a += 2) {
                unsigned bf[4];
                ldsm_x4(bf, bbase + ((nbase + (a << 3)) * 72 + (t << 4)) * 2 + b_loff);
                mma_f16(acc[0][a],     af[0], bf[0], bf[1]);
                mma_f16(acc[0][a + 1], af[0], bf[2], bf[3]);
                mma_f16(acc[1][a],     af[1], bf[0], bf[1]);
                mma_f16(acc[1][a + 1], af[1], bf[2], bf[3]);
            }
        }
    }

    const int rq = lane >> 2, cq = lane & 3;
#pragma unroll
    for (int mt = 0; mt < 2; mt++) {
#pragma unroll
        for (int nt = 0; nt < 8; nt++) {
            int r = m0 + mbase + (mt << 4) + rq;
            int c = n0 + nbase + (nt << 3) + (cq << 1);
            float b0 = bias[c], b1 = bias[c + 1];
            float v00 = acc[mt][nt][0] + b0, v01 = acc[mt][nt][1] + b1;
            float v10 = acc[mt][nt][2] + b0, v11 = acc[mt][nt][3] + b1;
            if (half_out) {
                __half* Ch = (__half*)Cout;
                *(__half2*)&Ch[(size_t)r * N + c]       = __floats2half2_rn(v00, v01);
                *(__half2*)&Ch[(size_t)(r + 8) * N + c] = __floats2half2_rn(v10, v11);
            } else {
                float* Cf = (float*)Cout;
                *(float2*)&Cf[(size_t)r * N + c]       = make_float2(v00, v01);
                *(float2*)&Cf[(size_t)(r + 8) * N + c] = make_float2(v10, v11);
            }
        }
    }
}

__global__ __launch_bounds__(256, 2)
void gemm_qkv_kernel(const __half* __restrict__ aq, const __half* __restrict__ ak,
                     const __half* __restrict__ av,
                     const __half* __restrict__ wq, const __half* __restrict__ wk,
                     const __half* __restrict__ wv,
                     const float* __restrict__ bq, const float* __restrict__ bk,
                     const float* __restrict__ bv,
                     __half* oq, __half* ok, __half* ov, int M, int N, int K)
{
    extern __shared__ __half gsm[];
    const int z = blockIdx.z;
    const __half* A = (z == 0) ? aq : (z == 1) ? ak : av;
    const __half* W = (z == 0) ? wq : (z == 1) ? wk : wv;
    const float* bias = (z == 0) ? bq : (z == 1) ? bk : bv;
    __half* O = (z == 0) ? oq : (z == 1) ? ok : ov;
    gemm_core(A, W, bias, O, M, N, K, 1, gsm);
}

__global__ __launch_bounds__(256, 2)
void gemm_out_kernel(const __half* __restrict__ A, const __half* __restrict__ W,
                     const float* __restrict__ bias, float* __restrict__ C,
                     int M, int N, int K)
{
    extern __shared__ __half gsm[];
    gemm_core(A, W, bias, C, M, N, K, 0, gsm);
}

// ---------------------------------------------------------------------------
// fp16 flash attention. CTA: 128 threads / 4 warps; Q tile 128 rows; each warp
// owns 32 rows as TWO m16 strips, so every K/V ldmatrix fragment feeds 2x MMAs.
// ---------------------------------------------------------------------------
#define Q_WORDS_ (128 * 72)
#define KV_WORDS_ (64 * 72)
#define ATTN_SMEM_BYTES ((Q_WORDS_ + 4 * KV_WORDS_) * 2)

__global__ __launch_bounds__(128, 2)
void attn_f16_kernel()
{
    extern __shared__ __half smh[];
    __half* Qs = smh;
    __half* Kb0 = smh + Q_WORDS_;
    __half* Kb1 = Kb0 + KV_WORDS_;
    __half* Vb0 = Kb1 + KV_WORDS_;
    __half* Vb1 = Vb0 + KV_WORDS_;

    const int tid = threadIdx.x;
    const int lane = tid & 31;
    const int wid = tid >> 5;               // 0..3
    const int wm = wid << 5;                // 32 rows per warp
    const int rq = lane >> 2, cq = lane & 3;
    const int q0 = blockIdx.x << 7;
    const int h = blockIdx.y, b = blockIdx.z;
    const size_t base = ((size_t)(b * H_ + h) * S_) * DK_;
    const __half* Qg = g_Qh + base;
    const __half* Kg = g_Kh + base;
    const __half* Vg = g_Vh + base;

    // permuted mask bases for the warp's two 16-row strips
    const size_t wt0 = (size_t)(b * 128 + (q0 >> 4) + wid * 2);
    const __half2* pm0s[2] = { g_pm0h + wt0 * 32 * 512 + lane,
                               g_pm0h + (wt0 + 1) * 32 * 512 + lane };
    const __half2* pm1s[2] = { g_pm1h + wt0 * 32 * 512 + lane,
                               g_pm1h + (wt0 + 1) * 32 * 512 + lane };

    unsigned ku[2], vu[2];
    ku[0] = (unsigned)__cvta_generic_to_shared(Kb0);
    ku[1] = (unsigned)__cvta_generic_to_shared(Kb1);
    vu[0] = (unsigned)__cvta_generic_to_shared(Vb0);
    vu[1] = (unsigned)__cvta_generic_to_shared(Vb1);

    const unsigned k_loff = ((((lane >> 4) & 1) * 8 + (lane & 7)) * 72 + ((lane >> 3) & 1) * 8) * 2;
    const unsigned v_loff = ((((lane >> 3) & 1) * 8 + (lane & 7)) * 72 + ((lane >> 4) & 1) * 8) * 2;

    // KV staging: 128 threads x 4 chunks cover 64 rows x 128B
    const int srow = tid >> 3, sc8 = (tid & 7) << 3;

#pragma unroll
    for (int i = 0; i < 4; i++) {
        int row = srow + i * 16;
        cp_async16(ku[0] + (row * 72 + sc8) * 2, Kg + row * 64 + sc8);
        cp_async16(vu[0] + (row * 72 + sc8) * 2, Vg + row * 64 + sc8);
    }
    cp_commit();

    // stage Q (128 rows)
#pragma unroll
    for (int i = 0; i < 8; i++) {
        int flat = tid + (i << 7);
        int row = flat >> 3, c8 = (flat & 7) << 3;
        *(uint4*)&Qs[row * 72 + c8] = *(const uint4*)&Qg[(size_t)(q0 + row) * 64 + c8];
    }
    cp_wait0();
    __syncthreads();

    // Q fragments: 2 strips x 4 k-chunks
    unsigned qf[2][4][4];
#pragma unroll
    for (int st = 0; st < 2; st++) {
#pragma unroll
        for (int t = 0; t < 4; t++) {
            const __half* qr = &Qs[(wm + (st << 4) + rq) * 72 + (t << 4) + (cq << 1)];
            qf[st][t][0] = *(const unsigned*)qr;
            qf[st][t][1] = *(const unsigned*)(qr + 8 * 72);
            qf[st][t][2] = *(const unsigned*)(qr + 8);
            qf[st][t][3] = *(const unsigned*)(qr + 8 * 72 + 8);
        }
    }

    float Z[2][2] = {};
    float oacc[2][8][4] = {};

    for (int kt = 0; kt < NT_; kt++) {
        const int cur = kt & 1;

        if (kt + 1 < NT_) {
            const __half* Kn = Kg + (size_t)((kt + 1) << 6) * 64;
            const __half* Vn = Vg + (size_t)((kt + 1) << 6) * 64;
            int nb = cur ^ 1;
#pragma unroll
            for (int i = 0; i < 4; i++) {
                int row = srow + i * 16;
                cp_async16(ku[nb] + (row * 72 + sc8) * 2, Kn + row * 64 + sc8);
                cp_async16(vu[nb] + (row * 72 + sc8) * 2, Vn + row * 64 + sc8);
            }
        }
        cp_commit();

        // S = Q @ K^T : each K fragment feeds both strips
        float sacc[2][8][4] = {};
#pragma unroll
        for (int t = 0; t < 4; t++) {
#pragma unroll
            for (int a = 0; a < 8; a += 2) {
                unsigned bf[4];
                ldsm_x4(bf, ku[cur] + ((a << 3) * 72 + (t << 4)) * 2 + k_loff);
                mma_f16(sacc[0][a],     qf[0][t], bf[0], bf[1]);
                mma_f16(sacc[0][a + 1], qf[0][t], bf[2], bf[3]);
                mma_f16(sacc[1][a],     qf[1][t], bf[0], bf[1]);
                mma_f16(sacc[1][a + 1], qf[1][t], bf[2], bf[3]);
            }
        }

        // Unshifted softmax per strip
        unsigned pf[2][4][4];
#pragma unroll
        for (int st = 0; st < 2; st++) {
            const __half2* p0 = pm0s[st] + kt * 512;
            const __half2* p1 = pm1s[st] + kt * 512;
#pragma unroll
            for (int t = 0; t < 4; t++) {
#pragma unroll
                for (int s = 0; s < 2; s++) {
                    int nt = (t << 1) + s;
                    float2 ma  = __half22float2(p0[nt << 5]);
                    float2 mb  = __half22float2(p0[(nt + 8) << 5]);
                    float2 m1a = __half22float2(p1[nt << 5]);
                    float2 m1b = __half22float2(p1[(nt + 8) << 5]);
                    float e0 = __expf(fmaf(sacc[st][nt][0], NORM_, ma.x));
                    float e1 = __expf(fmaf(sacc[st][nt][1], NORM_, ma.y));
                    float e2 = __expf(fmaf(sacc[st][nt][2], NORM_, mb.x));
                    float e3 = __expf(fmaf(sacc[st][nt][3], NORM_, mb.y));
                    Z[st][0] += e0 + e1;
                    Z[st][1] += e2 + e3;
                    pf[st][t][0 + s * 2] = h2u(__floats2half2_rn(e0 * m1a.x, e1 * m1a.y));
                    pf[st][t][1 + s * 2] = h2u(__floats2half2_rn(e2 * m1b.x, e3 * m1b.y));
                }
            }
        }

        // O += P @ V : each V fragment feeds both strips
#pragma unroll
        for (int t = 0; t < 4; t++) {
#pragma unroll
            for (int u = 0; u < 4; u++) {
                unsigned bf[4];
                ldsm_x4_t(bf, vu[cur] + ((t << 4) * 72 + (u << 4)) * 2 + v_loff);
                mma_f16(oacc[0][(u << 1)],     pf[0][t], bf[0], bf[1]);
                mma_f16(oacc[0][(u << 1) + 1], pf[0][t], bf[2], bf[3]);
                mma_f16(oacc[1][(u << 1)],     pf[1][t], bf[0], bf[1]);
                mma_f16(oacc[1][(u << 1) + 1], pf[1][t], bf[2], bf[3]);
            }
        }

        cp_wait0();
        __syncthreads();
    }

    __half* Og = g_ctxh + base;
#pragma unroll
    for (int st = 0; st < 2; st++) {
        float z0 = Z[st][0], z1 = Z[st][1];
        z0 += __shfl_xor_sync(0xffffffffu, z0, 1);
        z0 += __shfl_xor_sync(0xffffffffu, z0, 2);
        z1 += __shfl_xor_sync(0xffffffffu, z1, 1);
        z1 += __shfl_xor_sync(0xffffffffu, z1, 2);
        float i0 = 1.0f / z0, i1 = 1.0f / z1;
        int rbase = q0 + wm + (st << 4) + rq;
#pragma unroll
        for (int nt = 0; nt < 8; nt++) {
            int col = (nt << 3) + (cq << 1);
            *(__half2*)&Og[(size_t)rbase * 64 + col] =
                __floats2half2_rn(oacc[st][nt][0] * i0, oacc[st][nt][1] * i0);
            *(__half2*)&Og[(size_t)(rbase + 8) * 64 + col] =
                __floats2half2_rn(oacc[st][nt][2] * i1, oacc[st][nt][3] * i1);
        }
    }
}

extern "C" void kernel_launch(void* const* d_in, const int* in_sizes, int n_in,
                              void* d_out, int out_size)
{
    const float* q  = (const float*)d_in[0];
    const float* k  = (const float*)d_in[1];
    const float* v  = (const float*)d_in[2];
    const float* m0 = (const float*)d_in[3];
    const float* m1 = (const float*)d_in[4];
    const float* wq = (const float*)d_in[5];
    const float* bq = (const float*)d_in[6];
    const float* wk = (const float*)d_in[7];
    const float* bk = (const float*)d_in[8];
    const float* wv = (const float*)d_in[9];
    const float* bv = (const float*)d_in[10];
    const float* wo = (const float*)d_in[11];
    const float* bo = (const float*)d_in[12];

    void *pq16, *pk16, *pv16, *pwq, *pwk, *pwv, *pwo;
    void *pQh, *pKh, *pVh, *pCh, *ppm0, *ppm1;
    cudaGetSymbolAddress(&pq16, g_q16);
    cudaGetSymbolAddress(&pk16, g_k16);
    cudaGetSymbolAddress(&pv16, g_v16);
    cudaGetSymbolAddress(&pwq, g_wq16);
    cudaGetSymbolAddress(&pwk, g_wk16);
    cudaGetSymbolAddress(&pwv, g_wv16);
    cudaGetSymbolAddress(&pwo, g_wo16);
    cudaGetSymbolAddress(&pQh, g_Qh);
    cudaGetSymbolAddress(&pKh, g_Kh);
    cudaGetSymbolAddress(&pVh, g_Vh);
    cudaGetSymbolAddress(&pCh, g_ctxh);
    cudaGetSymbolAddress(&ppm0, g_pm0h);
    cudaGetSymbolAddress(&ppm1, g_pm1h);

    const int M = B_ * S_, N = D_, K = D_;

    f2h_multi_kernel<<<8192, 256>>>(q, k, v, wq, wk, wv, wo,
                                    (__half*)pq16, (__half*)pk16, (__half*)pv16,
                                    (__half*)pwq, (__half*)pwk, (__half*)pwv, (__half*)pwo);
    permute_masks_kernel<<<dim3(32, 128, B_), 512>>>(m0, m1, (__half2*)ppm0, (__half2*)ppm1);

    dim3 blk(256);
    cudaFuncSetAttribute(gemm_qkv_kernel, cudaFuncAttributeMaxDynamicSharedMemorySize,
                         GEMM_SMEM_BYTES);
    cudaFuncSetAttribute(gemm_out_kernel, cudaFuncAttributeMaxDynamicSharedMemorySize,
                         GEMM_SMEM_BYTES);

    gemm_qkv_kernel<<<dim3(N / 128, M / 128, 3), blk, GEMM_SMEM_BYTES>>>(
        (const __half*)pq16, (const __half*)pk16, (const __half*)pv16,
        (const __half*)pwq, (const __half*)pwk, (const __half*)pwv,
        bq, bk, bv,
        (__half*)pQh, (__half*)pKh, (__half*)pVh, M, N, K);

    cudaFuncSetAttribute(attn_f16_kernel, cudaFuncAttributeMaxDynamicSharedMemorySize,
                         ATTN_SMEM_BYTES);
    attn_f16_kernel<<<dim3(S_ / 128, H_, B_), dim3(128), ATTN_SMEM_BYTES>>>();

    gemm_out_kernel<<<dim3(N / 128, M / 128), blk, GEMM_SMEM_BYTES>>>(
        (const __half*)pCh, (const __half*)pwo, bo, (float*)d_out, M, N, K);
}

// round 9
// speedup vs baseline: 1.4332x; 1.4332x over previous
#include <cuda_runtime.h>
#include <cuda_fp16.h>
#include <math.h>

#define B_ 2
#define S_ 2048
#define D_ 1024
#define H_ 16
#define DK_ 64
#define NORM_ 0.125f
#define NT_ (S_ / 64)

// Scratch (allocation-free rule: device globals)
__device__ __half g_q16[(size_t)B_ * S_ * D_];
__device__ __half g_k16[(size_t)B_ * S_ * D_];
__device__ __half g_v16[(size_t)B_ * S_ * D_];
__device__ __half g_wq16[(size_t)D_ * D_];
__device__ __half g_wk16[(size_t)D_ * D_];
__device__ __half g_wv16[(size_t)D_ * D_];
__device__ __half g_wo16[(size_t)D_ * D_];
__device__ __half g_Qh[(size_t)B_ * S_ * D_];
__device__ __half g_Kh[(size_t)B_ * S_ * D_];
__device__ __half g_Vh[(size_t)B_ * S_ * D_];
__device__ __half g_ctxh[(size_t)B_ * S_ * D_];
// Combined permuted masks, fragment order: [b][wt(128)][kt(32)][chunk(16)][lane(32)]
// each record = { mask0 half2, mask1 half2 } packed in a uint2 (8 bytes).
__device__ uint2 g_pmc[(size_t)B_ * 128 * 32 * 512];

__device__ __forceinline__ void mma_f16(float c[4], const unsigned a[4], const unsigned b0, const unsigned b1) {
    asm volatile(
        "mma.sync.aligned.m16n8k16.row.col.f32.f16.f16.f32 "
        "{%0,%1,%2,%3}, {%4,%5,%6,%7}, {%8,%9}, {%0,%1,%2,%3};"
        : "+f"(c[0]), "+f"(c[1]), "+f"(c[2]), "+f"(c[3])
        : "r"(a[0]), "r"(a[1]), "r"(a[2]), "r"(a[3]), "r"(b0), "r"(b1));
}
__device__ __forceinline__ void ldsm_x4(unsigned d[4], unsigned addr) {
    asm volatile("ldmatrix.sync.aligned.m8n8.x4.shared.b16 {%0,%1,%2,%3}, [%4];"
                 : "=r"(d[0]), "=r"(d[1]), "=r"(d[2]), "=r"(d[3]) : "r"(addr));
}
__device__ __forceinline__ void ldsm_x4_t(unsigned d[4], unsigned addr) {
    asm volatile("ldmatrix.sync.aligned.m8n8.x4.trans.shared.b16 {%0,%1,%2,%3}, [%4];"
                 : "=r"(d[0]), "=r"(d[1]), "=r"(d[2]), "=r"(d[3]) : "r"(addr));
}
__device__ __forceinline__ void cp_async16(unsigned smem_dst, const void* gsrc) {
    asm volatile("cp.async.cg.shared.global [%0], [%1], 16;" :: "r"(smem_dst), "l"(gsrc));
}
__device__ __forceinline__ void cp_commit() { asm volatile("cp.async.commit_group;"); }
__device__ __forceinline__ void cp_wait0()  { asm volatile("cp.async.wait_group 0;"); }
__device__ __forceinline__ void cp_wait1()  { asm volatile("cp.async.wait_group 1;"); }
__device__ __forceinline__ unsigned h2u(__half2 h) { return *(unsigned*)&h; }
__device__ __forceinline__ __half2 u2h(unsigned u) { return *(__half2*)&u; }

// ---------------------------------------------------------------------------
// Fused pre-pass: convert 7 tensors fp32 -> fp16 in ONE launch.
// ---------------------------------------------------------------------------
__global__ __launch_bounds__(256)
void f2h_multi_kernel(const float* __restrict__ q, const float* __restrict__ k,
                      const float* __restrict__ v, const float* __restrict__ wq,
                      const float* __restrict__ wk, const float* __restrict__ wv,
                      const float* __restrict__ wo,
                      __half* dq, __half* dk, __half* dv,
                      __half* dwq, __half* dwk, __half* dwv, __half* dwo)
{
    int bx = blockIdx.x;
    const float* src; __half* dst; int base;
    if      (bx < 2048) { src = q;  dst = dq;  base = bx; }
    else if (bx < 4096) { src = k;  dst = dk;  base = bx - 2048; }
    else if (bx < 6144) { src = v;  dst = dv;  base = bx - 4096; }
    else if (bx < 6656) { src = wq; dst = dwq; base = bx - 6144; }
    else if (bx < 7168) { src = wk; dst = dwk; base = bx - 6656; }
    else if (bx < 7680) { src = wv; dst = dwv; base = bx - 7168; }
    else                { src = wo; dst = dwo; base = bx - 7680; }
    int i = (base * 256 + threadIdx.x) * 8;
    float4 a = *(const float4*)&src[i];
    float4 b = *(const float4*)&src[i + 4];
    uint4 o;
    o.x = h2u(__floats2half2_rn(a.x, a.y));
    o.y = h2u(__floats2half2_rn(a.z, a.w));
    o.z = h2u(__floats2half2_rn(b.x, b.y));
    o.w = h2u(__floats2half2_rn(b.z, b.w));
    *(uint4*)&dst[i] = o;
}

// ---------------------------------------------------------------------------
// Pre-pass: permute both masks into combined fragment-order records.
// ---------------------------------------------------------------------------
__global__ __launch_bounds__(512)
void permute_masks_kernel(const float* __restrict__ m0, const float* __restrict__ m1,
                          uint2* __restrict__ pmc)
{
    const int kt = blockIdx.x, wt = blockIdx.y, b = blockIdx.z;
    const int c = threadIdx.x >> 5, l = threadIdx.x & 31;
    const int rq = l >> 2, cq = l & 3;
    const int row = wt * 16 + rq + ((c >= 8) ? 8 : 0);
    const int col = kt * 64 + (c & 7) * 8 + cq * 2;
    const size_t soff = ((size_t)b * S_ + row) * S_ + col;
    const size_t doff = (((size_t)(b * 128 + wt)) * 32 + kt) * 512 + c * 32 + l;
    float2 a = *(const float2*)&m0[soff];
    float2 bb = *(const float2*)&m1[soff];
    pmc[doff] = make_uint2(h2u(__floats2half2_rn(a.x, a.y)),
                           h2u(__floats2half2_rn(bb.x, bb.y)));
}

// ---------------------------------------------------------------------------
// fp16 GEMM core, cp.async 2-stage, K-tile 64 (unchanged, known-good)
// ---------------------------------------------------------------------------
#define GST_ (128 * 72)
#define GEMM_SMEM_BYTES (4 * GST_ * 2)

__device__ __forceinline__
void gemm_core(const __half* __restrict__ A, const __half* __restrict__ W,
               const float* __restrict__ bias, void* __restrict__ Cout,
               int M, int N, int K, int half_out, __half* gsm)
{
    __half* As = gsm;
    __half* Bs = gsm + 2 * GST_;

    const int tid = threadIdx.x;
    const int lane = tid & 31;
    const int wid = tid >> 5;
    const int mbase = (wid & 3) << 5;
    const int nbase = (wid >> 2) << 6;
    const int m0 = blockIdx.y << 7;
    const int n0 = blockIdx.x << 7;

    const unsigned as_u = (unsigned)__cvta_generic_to_shared(As);
    const unsigned bs_u = (unsigned)__cvta_generic_to_shared(Bs);
    const unsigned a_loff = ((((lane >> 3) & 1) * 8 + (lane & 7)) * 72 + ((lane >> 4) & 1) * 8) * 2;
    const unsigned b_loff = ((((lane >> 4) & 1) * 8 + (lane & 7)) * 72 + ((lane >> 3) & 1) * 8) * 2;

    const int srow = tid >> 3;
    const int sc8 = (tid & 7) << 3;

    float acc[2][8][4] = {};
    const int NK = K / 64;

    {
#pragma unroll
        for (int i = 0; i < 4; i++) {
            int row = srow + i * 32;
            cp_async16(as_u + (row * 72 + sc8) * 2, A + (size_t)(m0 + row) * K + sc8);
            cp_async16(bs_u + (row * 72 + sc8) * 2, W + (size_t)(n0 + row) * K + sc8);
        }
        cp_commit();
    }

    for (int kk = 0; kk < NK; kk++) {
        const int buf = kk & 1;
        __syncthreads();
        if (kk + 1 < NK) {
            const int k0 = (kk + 1) << 6;
            unsigned off = (unsigned)((buf ^ 1) * GST_ * 2);
#pragma unroll
            for (int i = 0; i < 4; i++) {
                int row = srow + i * 32;
                cp_async16(as_u + off + (row * 72 + sc8) * 2, A + (size_t)(m0 + row) * K + k0 + sc8);
                cp_async16(bs_u + off + (row * 72 + sc8) * 2, W + (size_t)(n0 + row) * K + k0 + sc8);
            }
        }
        cp_commit();
        cp_wait1();
        __syncthreads();

        const unsigned abase = as_u + (unsigned)(buf * GST_ * 2);
        const unsigned bbase = bs_u + (unsigned)(buf * GST_ * 2);
#pragma unroll
        for (int t = 0; t < 4; t++) {
            unsigned af[2][4];
#pragma unroll
            for (int mt = 0; mt < 2; mt++)
                ldsm_x4(af[mt], abase + ((mbase + (mt << 4)) * 72 + (t << 4)) * 2 + a_loff);
#pragma unroll
            for (int a = 0; a < 8; a += 2) {
                unsigned bf[4];
                ldsm_x4(bf, bbase + ((nbase + (a << 3)) * 72 + (t << 4)) * 2 + b_loff);
                mma_f16(acc[0][a],     af[0], bf[0], bf[1]);
                mma_f16(acc[0][a + 1], af[0], bf[2], bf[3]);
                mma_f16(acc[1][a],     af[1], bf[0], bf[1]);
                mma_f16(acc[1][a + 1], af[1], bf[2], bf[3]);
            }
        }
    }

    const int rq = lane >> 2, cq = lane & 3;
#pragma unroll
    for (int mt = 0; mt < 2; mt++) {
#pragma unroll
        for (int nt = 0; nt < 8; nt++) {
            int r = m0 + mbase + (mt << 4) + rq;
            int c = n0 + nbase + (nt << 3) + (cq << 1);
            float b0 = bias[c], b1 = bias[c + 1];
            float v00 = acc[mt][nt][0] + b0, v01 = acc[mt][nt][1] + b1;
            float v10 = acc[mt][nt][2] + b0, v11 = acc[mt][nt][3] + b1;
            if (half_out) {
                __half* Ch = (__half*)Cout;
                *(__half2*)&Ch[(size_t)r * N + c]       = __floats2half2_rn(v00, v01);
                *(__half2*)&Ch[(size_t)(r + 8) * N + c] = __floats2half2_rn(v10, v11);
            } else {
                float* Cf = (float*)Cout;
                *(float2*)&Cf[(size_t)r * N + c]       = make_float2(v00, v01);
                *(float2*)&Cf[(size_t)(r + 8) * N + c] = make_float2(v10, v11);
            }
        }
    }
}

__global__ __launch_bounds__(256, 2)
void gemm_qkv_kernel(const __half* __restrict__ aq, const __half* __restrict__ ak,
                     const __half* __restrict__ av,
                     const __half* __restrict__ wq, const __half* __restrict__ wk,
                     const __half* __restrict__ wv,
                     const float* __restrict__ bq, const float* __restrict__ bk,
                     const float* __restrict__ bv,
                     __half* oq, __half* ok, __half* ov, int M, int N, int K)
{
    extern __shared__ __half gsm[];
    const int z = blockIdx.z;
    const __half* A = (z == 0) ? aq : (z == 1) ? ak : av;
    const __half* W = (z == 0) ? wq : (z == 1) ? wk : wv;
    const float* bias = (z == 0) ? bq : (z == 1) ? bk : bv;
    __half* O = (z == 0) ? oq : (z == 1) ? ok : ov;
    gemm_core(A, W, bias, O, M, N, K, 1, gsm);
}

__global__ __launch_bounds__(256, 2)
void gemm_out_kernel(const __half* __restrict__ A, const __half* __restrict__ W,
                     const float* __restrict__ bias, float* __restrict__ C,
                     int M, int N, int K)
{
    extern __shared__ __half gsm[];
    gemm_core(A, W, bias, C, M, N, K, 0, gsm);
}

// ---------------------------------------------------------------------------
// fp16 flash attention — R7 configuration (256 thr, 16-row warps) with
// combined mask records (one LDG.64 per record instead of two LDG.32).
// ---------------------------------------------------------------------------
#define Q_WORDS_ (128 * 72)
#define KV_WORDS_ (64 * 72)
#define ATTN_SMEM_BYTES ((Q_WORDS_ + 4 * KV_WORDS_) * 2)

__global__ __launch_bounds__(256, 2)
void attn_f16_kernel()
{
    extern __shared__ __half smh[];
    __half* Qs = smh;
    __half* Kb0 = smh + Q_WORDS_;
    __half* Kb1 = Kb0 + KV_WORDS_;
    __half* Vb0 = Kb1 + KV_WORDS_;
    __half* Vb1 = Vb0 + KV_WORDS_;

    const int tid = threadIdx.x;
    const int lane = tid & 31;
    const int wid = tid >> 5;
    const int wm = wid << 4;
    const int rq = lane >> 2, cq = lane & 3;
    const int q0 = blockIdx.x << 7;
    const int h = blockIdx.y, b = blockIdx.z;
    const size_t base = ((size_t)(b * H_ + h) * S_) * DK_;
    const __half* Qg = g_Qh + base;
    const __half* Kg = g_Kh + base;
    const __half* Vg = g_Vh + base;

    const size_t wt = (size_t)(b * 128 + (q0 >> 4) + wid);
    const uint2* pmc = g_pmc + wt * 32 * 512 + lane;

    unsigned ku[2], vu[2];
    ku[0] = (unsigned)__cvta_generic_to_shared(Kb0);
    ku[1] = (unsigned)__cvta_generic_to_shared(Kb1);
    vu[0] = (unsigned)__cvta_generic_to_shared(Vb0);
    vu[1] = (unsigned)__cvta_generic_to_shared(Vb1);

    const unsigned k_loff = ((((lane >> 4) & 1) * 8 + (lane & 7)) * 72 + ((lane >> 3) & 1) * 8) * 2;
    const unsigned v_loff = ((((lane >> 3) & 1) * 8 + (lane & 7)) * 72 + ((lane >> 4) & 1) * 8) * 2;

    const int srow0 = tid >> 3, sc8 = (tid & 7) << 3;
    const int srow1 = srow0 + 32;

    cp_async16(ku[0] + (srow0 * 72 + sc8) * 2, Kg + srow0 * 64 + sc8);
    cp_async16(ku[0] + (srow1 * 72 + sc8) * 2, Kg + srow1 * 64 + sc8);
    cp_async16(vu[0] + (srow0 * 72 + sc8) * 2, Vg + srow0 * 64 + sc8);
    cp_async16(vu[0] + (srow1 * 72 + sc8) * 2, Vg + srow1 * 64 + sc8);
    cp_commit();

#pragma unroll
    for (int i = 0; i < 4; i++) {
        int flat = tid + (i << 8);
        int row = flat >> 3, c8 = (flat & 7) << 3;
        *(uint4*)&Qs[row * 72 + c8] = *(const uint4*)&Qg[(size_t)(q0 + row) * 64 + c8];
    }
    cp_wait0();
    __syncthreads();

    unsigned qf[4][4];
#pragma unroll
    for (int t = 0; t < 4; t++) {
        const __half* qr = &Qs[(wm + rq) * 72 + (t << 4) + (cq << 1)];
        qf[t][0] = *(const unsigned*)qr;
        qf[t][1] = *(const unsigned*)(qr + 8 * 72);
        qf[t][2] = *(const unsigned*)(qr + 8);
        qf[t][3] = *(const unsigned*)(qr + 8 * 72 + 8);
    }

    float Z0 = 0.0f, Z1 = 0.0f;
    float oacc[8][4] = {};

    for (int kt = 0; kt < NT_; kt++) {
        const int cur = kt & 1;

        if (kt + 1 < NT_) {
            const __half* Kn = Kg + (size_t)((kt + 1) << 6) * 64;
            const __half* Vn = Vg + (size_t)((kt + 1) << 6) * 64;
            int nb = cur ^ 1;
            cp_async16(ku[nb] + (srow0 * 72 + sc8) * 2, Kn + srow0 * 64 + sc8);
            cp_async16(ku[nb] + (srow1 * 72 + sc8) * 2, Kn + srow1 * 64 + sc8);
            cp_async16(vu[nb] + (srow0 * 72 + sc8) * 2, Vn + srow0 * 64 + sc8);
            cp_async16(vu[nb] + (srow1 * 72 + sc8) * 2, Vn + srow1 * 64 + sc8);
        }
        cp_commit();

        // S = Q @ K^T
        float sacc[8][4] = {};
#pragma unroll
        for (int t = 0; t < 4; t++) {
#pragma unroll
            for (int a = 0; a < 8; a += 2) {
                unsigned bf[4];
                ldsm_x4(bf, ku[cur] + ((a << 3) * 72 + (t << 4)) * 2 + k_loff);
                mma_f16(sacc[a],     qf[t], bf[0], bf[1]);
                mma_f16(sacc[a + 1], qf[t], bf[2], bf[3]);
            }
        }

        // Unshifted softmax: e = exp(s*NORM + mask0); Z += e; P = e*mask1
        const uint2* pc = pmc + kt * 512;
        unsigned pf[4][4];
#pragma unroll
        for (int t = 0; t < 4; t++) {
#pragma unroll
            for (int s = 0; s < 2; s++) {
                int nt = (t << 1) + s;
                uint2 ra = pc[nt << 5];
                uint2 rb = pc[(nt + 8) << 5];
                float2 ma  = __half22float2(u2h(ra.x));
                float2 m1a = __half22float2(u2h(ra.y));
                float2 mb  = __half22float2(u2h(rb.x));
                float2 m1b = __half22float2(u2h(rb.y));
                float e0 = __expf(fmaf(sacc[nt][0], NORM_, ma.x));
                float e1 = __expf(fmaf(sacc[nt][1], NORM_, ma.y));
                float e2 = __expf(fmaf(sacc[nt][2], NORM_, mb.x));
                float e3 = __expf(fmaf(sacc[nt][3], NORM_, mb.y));
                Z0 += e0 + e1;
                Z1 += e2 + e3;
                pf[t][0 + s * 2] = h2u(__floats2half2_rn(e0 * m1a.x, e1 * m1a.y));
                pf[t][1 + s * 2] = h2u(__floats2half2_rn(e2 * m1b.x, e3 * m1b.y));
            }
        }

        // O += P @ V
#pragma unroll
        for (int t = 0; t < 4; t++) {
#pragma unroll
            for (int u = 0; u < 4; u++) {
                unsigned bf[4];
                ldsm_x4_t(bf, vu[cur] + ((t << 4) * 72 + (u << 4)) * 2 + v_loff);
                mma_f16(oacc[(u << 1)],     pf[t], bf[0], bf[1]);
                mma_f16(oacc[(u << 1) + 1], pf[t], bf[2], bf[3]);
            }
        }

        cp_wait0();
        __syncthreads();
    }

    Z0 += __shfl_xor_sync(0xffffffffu, Z0, 1);
    Z0 += __shfl_xor_sync(0xffffffffu, Z0, 2);
    Z1 += __shfl_xor_sync(0xffffffffu, Z1, 1);
    Z1 += __shfl_xor_sync(0xffffffffu, Z1, 2);
    float i0 = 1.0f / Z0, i1 = 1.0f / Z1;

    __half* Og = g_ctxh + base;
#pragma unroll
    for (int nt = 0; nt < 8; nt++) {
        int col = (nt << 3) + (cq << 1);
        *(__half2*)&Og[(size_t)(q0 + wm + rq) * 64 + col] =
            __floats2half2_rn(oacc[nt][0] * i0, oacc[nt][1] * i0);
        *(__half2*)&Og[(size_t)(q0 + wm + rq + 8) * 64 + col] =
            __floats2half2_rn(oacc[nt][2] * i1, oacc[nt][3] * i1);
    }
}

// ---------------------------------------------------------------------------
// Host side: stream fork so the mask permute overlaps f2h + QKV GEMM.
// Streams/events created once; every call records an identical graph.
// ---------------------------------------------------------------------------
static cudaStream_t s_side = nullptr;
static cudaEvent_t s_evFork = nullptr, s_evJoin = nullptr;

extern "C" void kernel_launch(void* const* d_in, const int* in_sizes, int n_in,
                              void* d_out, int out_size)
{
    if (!s_side) {
        cudaStreamCreateWithFlags(&s_side, cudaStreamNonBlocking);
        cudaEventCreateWithFlags(&s_evFork, cudaEventDisableTiming);
        cudaEventCreateWithFlags(&s_evJoin, cudaEventDisableTiming);
    }

    const float* q  = (const float*)d_in[0];
    const float* k  = (const float*)d_in[1];
    const float* v  = (const float*)d_in[2];
    const float* m0 = (const float*)d_in[3];
    const float* m1 = (const float*)d_in[4];
    const float* wq = (const float*)d_in[5];
    const float* bq = (const float*)d_in[6];
    const float* wk = (const float*)d_in[7];
    const float* bk = (const float*)d_in[8];
    const float* wv = (const float*)d_in[9];
    const float* bv = (const float*)d_in[10];
    const float* wo = (const float*)d_in[11];
    const float* bo = (const float*)d_in[12];

    void *pq16, *pk16, *pv16, *pwq, *pwk, *pwv, *pwo;
    void *pQh, *pKh, *pVh, *pCh, *ppmc;
    cudaGetSymbolAddress(&pq16, g_q16);
    cudaGetSymbolAddress(&pk16, g_k16);
    cudaGetSymbolAddress(&pv16, g_v16);
    cudaGetSymbolAddress(&pwq, g_wq16);
    cudaGetSymbolAddress(&pwk, g_wk16);
    cudaGetSymbolAddress(&pwv, g_wv16);
    cudaGetSymbolAddress(&pwo, g_wo16);
    cudaGetSymbolAddress(&pQh, g_Qh);
    cudaGetSymbolAddress(&pKh, g_Kh);
    cudaGetSymbolAddress(&pVh, g_Vh);
    cudaGetSymbolAddress(&pCh, g_ctxh);
    cudaGetSymbolAddress(&ppmc, g_pmc);

    const int M = B_ * S_, N = D_, K = D_;

    cudaFuncSetAttribute(gemm_qkv_kernel, cudaFuncAttributeMaxDynamicSharedMemorySize,
                         GEMM_SMEM_BYTES);
    cudaFuncSetAttribute(gemm_out_kernel, cudaFuncAttributeMaxDynamicSharedMemorySize,
                         GEMM_SMEM_BYTES);
    cudaFuncSetAttribute(attn_f16_kernel, cudaFuncAttributeMaxDynamicSharedMemorySize,
                         ATTN_SMEM_BYTES);

    // Fork: mask permute on the side stream, overlapping f2h + QKV GEMM.
    cudaEventRecord(s_evFork, 0);
    cudaStreamWaitEvent(s_side, s_evFork, 0);
    permute_masks_kernel<<<dim3(32, 128, B_), 512, 0, s_side>>>(m0, m1, (uint2*)ppmc);
    cudaEventRecord(s_evJoin, s_side);

    // Main stream: convert inputs, QKV projection.
    f2h_multi_kernel<<<8192, 256>>>(q, k, v, wq, wk, wv, wo,
                                    (__half*)pq16, (__half*)pk16, (__half*)pv16,
                                    (__half*)pwq, (__half*)pwk, (__half*)pwv, (__half*)pwo);

    dim3 blk(256);
    gemm_qkv_kernel<<<dim3(N / 128, M / 128, 3), blk, GEMM_SMEM_BYTES>>>(
        (const __half*)pq16, (const __half*)pk16, (const __half*)pv16,
        (const __half*)pwq, (const __half*)pwk, (const __half*)pwv,
        bq, bk, bv,
        (__half*)pQh, (__half*)pKh, (__half*)pVh, M, N, K);

    // Join: attention needs both QKV (main) and permuted masks (side).
    cudaStreamWaitEvent(0, s_evJoin, 0);
    attn_f16_kernel<<<dim3(S_ / 128, H_, B_), blk, ATTN_SMEM_BYTES>>>();

    gemm_out_kernel<<<dim3(N / 128, M / 128), blk, GEMM_SMEM_BYTES>>>(
        (const __half*)pCh, (const __half*)pwo, bo, (float*)d_out, M, N, K);
}

// round 11
// speedup vs baseline: 1.4811x; 1.0335x over previous
#include <cuda_runtime.h>
#include <cuda_fp16.h>
#include <math.h>

#define B_ 2
#define S_ 2048
#define D_ 1024
#define H_ 16
#define DK_ 64
#define NORM_ 0.125f
#define NT_ (S_ / 64)

// Scratch (allocation-free rule: device globals)
__device__ __half g_q16[(size_t)B_ * S_ * D_];
__device__ __half g_k16[(size_t)B_ * S_ * D_];
__device__ __half g_v16[(size_t)B_ * S_ * D_];
__device__ __half g_wq16[(size_t)D_ * D_];
__device__ __half g_wk16[(size_t)D_ * D_];
__device__ __half g_wv16[(size_t)D_ * D_];
__device__ __half g_wo16[(size_t)D_ * D_];
__device__ __half g_Qh[(size_t)B_ * S_ * D_];
__device__ __half g_Kh[(size_t)B_ * S_ * D_];
__device__ __half g_Vh[(size_t)B_ * S_ * D_];
__device__ __half g_ctxh[(size_t)B_ * S_ * D_];
// Permuted masks, fragment order, fp16: [b][wt(128)][kt(32)][chunk(16)][lane(32)] half2
__device__ __half2 g_pm0h[(size_t)B_ * 128 * 32 * 512];
__device__ __half2 g_pm1h[(size_t)B_ * 128 * 32 * 512];

__device__ __forceinline__ void mma_f16(float c[4], const unsigned a[4], const unsigned b0, const unsigned b1) {
    asm volatile(
        "mma.sync.aligned.m16n8k16.row.col.f32.f16.f16.f32 "
        "{%0,%1,%2,%3}, {%4,%5,%6,%7}, {%8,%9}, {%0,%1,%2,%3};"
        : "+f"(c[0]), "+f"(c[1]), "+f"(c[2]), "+f"(c[3])
        : "r"(a[0]), "r"(a[1]), "r"(a[2]), "r"(a[3]), "r"(b0), "r"(b1));
}
__device__ __forceinline__ void ldsm_x4(unsigned d[4], unsigned addr) {
    asm volatile("ldmatrix.sync.aligned.m8n8.x4.shared.b16 {%0,%1,%2,%3}, [%4];"
                 : "=r"(d[0]), "=r"(d[1]), "=r"(d[2]), "=r"(d[3]) : "r"(addr));
}
__device__ __forceinline__ void ldsm_x4_t(unsigned d[4], unsigned addr) {
    asm volatile("ldmatrix.sync.aligned.m8n8.x4.trans.shared.b16 {%0,%1,%2,%3}, [%4];"
                 : "=r"(d[0]), "=r"(d[1]), "=r"(d[2]), "=r"(d[3]) : "r"(addr));
}
__device__ __forceinline__ void cp_async16(unsigned smem_dst, const void* gsrc) {
    asm volatile("cp.async.cg.shared.global [%0], [%1], 16;" :: "r"(smem_dst), "l"(gsrc));
}
__device__ __forceinline__ void cp_commit() { asm volatile("cp.async.commit_group;"); }
__device__ __forceinline__ void cp_wait0()  { asm volatile("cp.async.wait_group 0;"); }
__device__ __forceinline__ void cp_wait1()  { asm volatile("cp.async.wait_group 1;"); }
__device__ __forceinline__ unsigned h2u(__half2 h) { return *(unsigned*)&h; }

// ---------------------------------------------------------------------------
// Fused pre-pass: 7x fp32->fp16 conversion AND mask permute in ONE launch.
// Blocks [0,4096): conversions (512 thr x 8 elems = 4096 elems/block).
// Blocks [4096,12288): mask permute (R7 layout, fp16).
// ---------------------------------------------------------------------------
__global__ __launch_bounds__(512)
void prepass_kernel(const float* __restrict__ q, const float* __restrict__ k,
                    const float* __restrict__ v, const float* __restrict__ wq,
                    const float* __restrict__ wk, const float* __restrict__ wv,
                    const float* __restrict__ wo,
                    const float* __restrict__ m0, const float* __restrict__ m1,
                    __half* dq, __half* dk, __half* dv,
                    __half* dwq, __half* dwk, __half* dwv, __half* dwo,
                    __half2* pm0, __half2* pm1)
{
    const int bx = blockIdx.x;
    const int tid = threadIdx.x;
    if (bx < 4096) {
        const float* src; __half* dst; int base;
        if      (bx < 1024) { src = q;  dst = dq;  base = bx; }
        else if (bx < 2048) { src = k;  dst = dk;  base = bx - 1024; }
        else if (bx < 3072) { src = v;  dst = dv;  base = bx - 2048; }
        else if (bx < 3328) { src = wq; dst = dwq; base = bx - 3072; }
        else if (bx < 3584) { src = wk; dst = dwk; base = bx - 3328; }
        else if (bx < 3840) { src = wv; dst = dwv; base = bx - 3584; }
        else                { src = wo; dst = dwo; base = bx - 3840; }
        int i = (base * 512 + tid) * 8;
        float4 a = *(const float4*)&src[i];
        float4 b = *(const float4*)&src[i + 4];
        uint4 o;
        o.x = h2u(__floats2half2_rn(a.x, a.y));
        o.y = h2u(__floats2half2_rn(a.z, a.w));
        o.z = h2u(__floats2half2_rn(b.x, b.y));
        o.w = h2u(__floats2half2_rn(b.z, b.w));
        *(uint4*)&dst[i] = o;
    } else {
        const int pbx = bx - 4096;
        const int kt = pbx & 31;
        const int wt = (pbx >> 5) & 127;
        const int b = pbx >> 12;
        const int c = tid >> 5, l = tid & 31;
        const int rq = l >> 2, cq = l & 3;
        const int row = wt * 16 + rq + ((c >= 8) ? 8 : 0);
        const int col = kt * 64 + (c & 7) * 8 + cq * 2;
        const size_t soff = ((size_t)b * S_ + row) * S_ + col;
        const size_t doff = (((size_t)(b * 128 + wt)) * 32 + kt) * 512 + c * 32 + l;
        float2 a = *(const float2*)&m0[soff];
        float2 bb = *(const float2*)&m1[soff];
        pm0[doff] = __floats2half2_rn(a.x, a.y);
        pm1[doff] = __floats2half2_rn(bb.x, bb.y);
    }
}

// ---------------------------------------------------------------------------
// fp16 GEMM core, cp.async 3-stage, K-tile 64, ONE syncthreads per iter.
// Tile 128x128, 8 warps (32m x 64n). Smem stride 72 halves, dynamic smem.
// ---------------------------------------------------------------------------
#define GSTG_ (128 * 72)                    // halves per matrix per stage
#define GEMM_SMEM_BYTES (6 * GSTG_ * 2)     // 3 stages x (A + W) = 110592 B

__device__ __forceinline__
void gemm_fill(unsigned as_u, unsigned bs_u, int s,
               const __half* __restrict__ A, const __half* __restrict__ W,
               int m0, int n0, int K, int kc, int tid)
{
    const unsigned off = (unsigned)(s * GSTG_ * 2);
    const int srow = tid >> 3;
    const int sc8 = (tid & 7) << 3;
#pragma unroll
    for (int i = 0; i < 4; i++) {
        int row = srow + i * 32;
        cp_async16(as_u + off + (row * 72 + sc8) * 2, A + (size_t)(m0 + row) * K + kc * 64 + sc8);
        cp_async16(bs_u + off + (row * 72 + sc8) * 2, W + (size_t)(n0 + row) * K + kc * 64 + sc8);
    }
}

__device__ __forceinline__
void gemm_core(const __half* __restrict__ A, const __half* __restrict__ W,
               const float* __restrict__ bias, void* __restrict__ Cout,
               int M, int N, int K, int half_out, __half* gsm)
{
    __half* As = gsm;                 // 3 stages
    __half* Bs = gsm + 3 * GSTG_;

    const int tid = threadIdx.x;
    const int lane = tid & 31;
    const int wid = tid >> 5;
    const int mbase = (wid & 3) << 5;
    const int nbase = (wid >> 2) << 6;
    const int m0 = blockIdx.y << 7;
    const int n0 = blockIdx.x << 7;

    const unsigned as_u = (unsigned)__cvta_generic_to_shared(As);
    const unsigned bs_u = (unsigned)__cvta_generic_to_shared(Bs);
    const unsigned a_loff = ((((lane >> 3) & 1) * 8 + (lane & 7)) * 72 + ((lane >> 4) & 1) * 8) * 2;
    const unsigned b_loff = ((((lane >> 4) & 1) * 8 + (lane & 7)) * 72 + ((lane >> 3) & 1) * 8) * 2;

    float acc[2][8][4] = {};
    const int NK = K / 64;

    // prologue: stages 0 and 1
    gemm_fill(as_u, bs_u, 0, A, W, m0, n0, K, 0, tid); cp_commit();
    gemm_fill(as_u, bs_u, 1, A, W, m0, n0, K, 1, tid); cp_commit();

    for (int kk = 0; kk < NK; kk++) {
        const int buf = kk % 3;
        cp_wait1();          // this thread's group for stage kk complete
        __syncthreads();     // all threads' waits done; prior compute done
        if (kk + 2 < NK)
            gemm_fill(as_u, bs_u, (kk + 2) % 3, A, W, m0, n0, K, kk + 2, tid);
        cp_commit();

        const unsigned abase = as_u + (unsigned)(buf * GSTG_ * 2);
        const unsigned bbase = bs_u + (unsigned)(buf * GSTG_ * 2);
#pragma unroll
        for (int t = 0; t < 4; t++) {
            unsigned af[2][4];
#pragma unroll
            for (int mt = 0; mt < 2; mt++)
                ldsm_x4(af[mt], abase + ((mbase + (mt << 4)) * 72 + (t << 4)) * 2 + a_loff);
#pragma unroll
            for (int a = 0; a < 8; a += 2) {
                unsigned bf[4];
                ldsm_x4(bf, bbase + ((nbase + (a << 3)) * 72 + (t << 4)) * 2 + b_loff);
                mma_f16(acc[0][a],     af[0], bf[0], bf[1]);
                mma_f16(acc[0][a + 1], af[0], bf[2], bf[3]);
                mma_f16(acc[1][a],     af[1], bf[0], bf[1]);
                mma_f16(acc[1][a + 1], af[1], bf[2], bf[3]);
            }
        }
    }

    const int rq = lane >> 2, cq = lane & 3;
#pragma unroll
    for (int mt = 0; mt < 2; mt++) {
#pragma unroll
        for (int nt = 0; nt < 8; nt++) {
            int r = m0 + mbase + (mt << 4) + rq;
            int c = n0 + nbase + (nt << 3) + (cq << 1);
            float b0 = bias[c], b1 = bias[c + 1];
            float v00 = acc[mt][nt][0] + b0, v01 = acc[mt][nt][1] + b1;
            float v10 = acc[mt][nt][2] + b0, v11 = acc[mt][nt][3] + b1;
            if (half_out) {
                __half* Ch = (__half*)Cout;
                *(__half2*)&Ch[(size_t)r * N + c]       = __floats2half2_rn(v00, v01);
                *(__half2*)&Ch[(size_t)(r + 8) * N + c] = __floats2half2_rn(v10, v11);
            } else {
                float* Cf = (float*)Cout;
                *(float2*)&Cf[(size_t)r * N + c]       = make_float2(v00, v01);
                *(float2*)&Cf[(size_t)(r + 8) * N + c] = make_float2(v10, v11);
            }
        }
    }
}

__global__ __launch_bounds__(256, 2)
void gemm_qkv_kernel(const __half* __restrict__ aq, const __half* __restrict__ ak,
                     const __half* __restrict__ av,
                     const __half* __restrict__ wq, const __half* __restrict__ wk,
                     const __half* __restrict__ wv,
                     const float* __restrict__ bq, const float* __restrict__ bk,
                     const float* __restrict__ bv,
                     __half* oq, __half* ok, __half* ov, int M, int N, int K)
{
    extern __shared__ __half gsm[];
    const int z = blockIdx.z;
    const __half* A = (z == 0) ? aq : (z == 1) ? ak : av;
    const __half* W = (z == 0) ? wq : (z == 1) ? wk : wv;
    const float* bias = (z == 0) ? bq : (z == 1) ? bk : bv;
    __half* O = (z == 0) ? oq : (z == 1) ? ok : ov;
    gemm_core(A, W, bias, O, M, N, K, 1, gsm);
}

__global__ __launch_bounds__(256, 2)
void gemm_out_kernel(const __half* __restrict__ A, const __half* __restrict__ W,
                     const float* __restrict__ bias, float* __restrict__ C,
                     int M, int N, int K)
{
    extern __shared__ __half gsm[];
    gemm_core(A, W, bias, C, M, N, K, 0, gsm);
}

// ---------------------------------------------------------------------------
// fp16 flash attention — R7 exact (256 thr, 16-row warps, fp16 permuted masks,
// no-max softmax). Known good: 148 us.
// ---------------------------------------------------------------------------
#define Q_WORDS_ (128 * 72)
#define KV_WORDS_ (64 * 72)
#define ATTN_SMEM_BYTES ((Q_WORDS_ + 4 * KV_WORDS_) * 2)

__global__ __launch_bounds__(256, 2)
void attn_f16_kernel()
{
    extern __shared__ __half smh[];
    __half* Qs = smh;
    __half* Kb0 = smh + Q_WORDS_;
    __half* Kb1 = Kb0 + KV_WORDS_;
    __half* Vb0 = Kb1 + KV_WORDS_;
    __half* Vb1 = Vb0 + KV_WORDS_;

    const int tid = threadIdx.x;
    const int lane = tid & 31;
    const int wid = tid >> 5;
    const int wm = wid << 4;
    const int rq = lane >> 2, cq = lane & 3;
    const int q0 = blockIdx.x << 7;
    const int h = blockIdx.y, b = blockIdx.z;
    const size_t base = ((size_t)(b * H_ + h) * S_) * DK_;
    const __half* Qg = g_Qh + base;
    const __half* Kg = g_Kh + base;
    const __half* Vg = g_Vh + base;

    const size_t wt = (size_t)(b * 128 + (q0 >> 4) + wid);
    const __half2* pm0 = g_pm0h + wt * 32 * 512 + lane;
    const __half2* pm1 = g_pm1h + wt * 32 * 512 + lane;

    unsigned ku[2], vu[2];
    ku[0] = (unsigned)__cvta_generic_to_shared(Kb0);
    ku[1] = (unsigned)__cvta_generic_to_shared(Kb1);
    vu[0] = (unsigned)__cvta_generic_to_shared(Vb0);
    vu[1] = (unsigned)__cvta_generic_to_shared(Vb1);

    const unsigned k_loff = ((((lane >> 4) & 1) * 8 + (lane & 7)) * 72 + ((lane >> 3) & 1) * 8) * 2;
    const unsigned v_loff = ((((lane >> 3) & 1) * 8 + (lane & 7)) * 72 + ((lane >> 4) & 1) * 8) * 2;

    const int srow0 = tid >> 3, sc8 = (tid & 7) << 3;
    const int srow1 = srow0 + 32;

    cp_async16(ku[0] + (srow0 * 72 + sc8) * 2, Kg + srow0 * 64 + sc8);
    cp_async16(ku[0] + (srow1 * 72 + sc8) * 2, Kg + srow1 * 64 + sc8);
    cp_async16(vu[0] + (srow0 * 72 + sc8) * 2, Vg + srow0 * 64 + sc8);
    cp_async16(vu[0] + (srow1 * 72 + sc8) * 2, Vg + srow1 * 64 + sc8);
    cp_commit();

#pragma unroll
    for (int i = 0; i < 4; i++) {
        int flat = tid + (i << 8);
        int row = flat >> 3, c8 = (flat & 7) << 3;
        *(uint4*)&Qs[row * 72 + c8] = *(const uint4*)&Qg[(size_t)(q0 + row) * 64 + c8];
    }
    cp_wait0();
    __syncthreads();

    unsigned qf[4][4];
#pragma unroll
    for (int t = 0; t < 4; t++) {
        const __half* qr = &Qs[(wm + rq) * 72 + (t << 4) + (cq << 1)];
        qf[t][0] = *(const unsigned*)qr;
        qf[t][1] = *(const unsigned*)(qr + 8 * 72);
        qf[t][2] = *(const unsigned*)(qr + 8);
        qf[t][3] = *(const unsigned*)(qr + 8 * 72 + 8);
    }

    float Z0 = 0.0f, Z1 = 0.0f;
    float oacc[8][4] = {};

    for (int kt = 0; kt < NT_; kt++) {
        const int cur = kt & 1;

        if (kt + 1 < NT_) {
            const __half* Kn = Kg + (size_t)((kt + 1) << 6) * 64;
            const __half* Vn = Vg + (size_t)((kt + 1) << 6) * 64;
            int nb = cur ^ 1;
            cp_async16(ku[nb] + (srow0 * 72 + sc8) * 2, Kn + srow0 * 64 + sc8);
            cp_async16(ku[nb] + (srow1 * 72 + sc8) * 2, Kn + srow1 * 64 + sc8);
            cp_async16(vu[nb] + (srow0 * 72 + sc8) * 2, Vn + srow0 * 64 + sc8);
            cp_async16(vu[nb] + (srow1 * 72 + sc8) * 2, Vn + srow1 * 64 + sc8);
        }
        cp_commit();

        // S = Q @ K^T
        float sacc[8][4] = {};
#pragma unroll
        for (int t = 0; t < 4; t++) {
#pragma unroll
            for (int a = 0; a < 8; a += 2) {
                unsigned bf[4];
                ldsm_x4(bf, ku[cur] + ((a << 3) * 72 + (t << 4)) * 2 + k_loff);
                mma_f16(sacc[a],     qf[t], bf[0], bf[1]);
                mma_f16(sacc[a + 1], qf[t], bf[2], bf[3]);
            }
        }

        // Unshifted softmax: e = exp(s*NORM + mask0); Z += e; P = e*mask1
        const __half2* p0 = pm0 + kt * 512;
        const __half2* p1 = pm1 + kt * 512;
        unsigned pf[4][4];
#pragma unroll
        for (int t = 0; t < 4; t++) {
#pragma unroll
            for (int s = 0; s < 2; s++) {
                int nt = (t << 1) + s;
                float2 ma  = __half22float2(p0[nt << 5]);
                float2 mb  = __half22float2(p0[(nt + 8) << 5]);
                float2 m1a = __half22float2(p1[nt << 5]);
                float2 m1b = __half22float2(p1[(nt + 8) << 5]);
                float e0 = __expf(fmaf(sacc[nt][0], NORM_, ma.x));
                float e1 = __expf(fmaf(sacc[nt][1], NORM_, ma.y));
                float e2 = __expf(fmaf(sacc[nt][2], NORM_, mb.x));
                float e3 = __expf(fmaf(sacc[nt][3], NORM_, mb.y));
                Z0 += e0 + e1;
                Z1 += e2 + e3;
                pf[t][0 + s * 2] = h2u(__floats2half2_rn(e0 * m1a.x, e1 * m1a.y));
                pf[t][1 + s * 2] = h2u(__floats2half2_rn(e2 * m1b.x, e3 * m1b.y));
            }
        }

        // O += P @ V
#pragma unroll
        for (int t = 0; t < 4; t++) {
#pragma unroll
            for (int u = 0; u < 4; u++) {
                unsigned bf[4];
                ldsm_x4_t(bf, vu[cur] + ((t << 4) * 72 + (u << 4)) * 2 + v_loff);
                mma_f16(oacc[(u << 1)],     pf[t], bf[0], bf[1]);
                mma_f16(oacc[(u << 1) + 1], pf[t], bf[2], bf[3]);
            }
        }

        cp_wait0();
        __syncthreads();
    }

    Z0 += __shfl_xor_sync(0xffffffffu, Z0, 1);
    Z0 += __shfl_xor_sync(0xffffffffu, Z0, 2);
    Z1 += __shfl_xor_sync(0xffffffffu, Z1, 1);
    Z1 += __shfl_xor_sync(0xffffffffu, Z1, 2);
    float i0 = 1.0f / Z0, i1 = 1.0f / Z1;

    __half* Og = g_ctxh + base;
#pragma unroll
    for (int nt = 0; nt < 8; nt++) {
        int col = (nt << 3) + (cq << 1);
        *(__half2*)&Og[(size_t)(q0 + wm + rq) * 64 + col] =
            __floats2half2_rn(oacc[nt][0] * i0, oacc[nt][1] * i0);
        *(__half2*)&Og[(size_t)(q0 + wm + rq + 8) * 64 + col] =
            __floats2half2_rn(oacc[nt][2] * i1, oacc[nt][3] * i1);
    }
}

extern "C" void kernel_launch(void* const* d_in, const int* in_sizes, int n_in,
                              void* d_out, int out_size)
{
    const float* q  = (const float*)d_in[0];
    const float* k  = (const float*)d_in[1];
    const float* v  = (const float*)d_in[2];
    const float* m0 = (const float*)d_in[3];
    const float* m1 = (const float*)d_in[4];
    const float* wq = (const float*)d_in[5];
    const float* bq = (const float*)d_in[6];
    const float* wk = (const float*)d_in[7];
    const float* bk = (const float*)d_in[8];
    const float* wv = (const float*)d_in[9];
    const float* bv = (const float*)d_in[10];
    const float* wo = (const float*)d_in[11];
    const float* bo = (const float*)d_in[12];

    void *pq16, *pk16, *pv16, *pwq, *pwk, *pwv, *pwo;
    void *pQh, *pKh, *pVh, *pCh, *ppm0, *ppm1;
    cudaGetSymbolAddress(&pq16, g_q16);
    cudaGetSymbolAddress(&pk16, g_k16);
    cudaGetSymbolAddress(&pv16, g_v16);
    cudaGetSymbolAddress(&pwq, g_wq16);
    cudaGetSymbolAddress(&pwk, g_wk16);
    cudaGetSymbolAddress(&pwv, g_wv16);
    cudaGetSymbolAddress(&pwo, g_wo16);
    cudaGetSymbolAddress(&pQh, g_Qh);
    cudaGetSymbolAddress(&pKh, g_Kh);
    cudaGetSymbolAddress(&pVh, g_Vh);
    cudaGetSymbolAddress(&pCh, g_ctxh);
    cudaGetSymbolAddress(&ppm0, g_pm0h);
    cudaGetSymbolAddress(&ppm1, g_pm1h);

    const int M = B_ * S_, N = D_, K = D_;

    // Single fused pre-pass launch (conversions + mask permute)
    prepass_kernel<<<12288, 512>>>(q, k, v, wq, wk, wv, wo, m0, m1,
                                   (__half*)pq16, (__half*)pk16, (__half*)pv16,
                                   (__half*)pwq, (__half*)pwk, (__half*)pwv, (__half*)pwo,
                                   (__half2*)ppm0, (__half2*)ppm1);

    dim3 blk(256);
    cudaFuncSetAttribute(gemm_qkv_kernel, cudaFuncAttributeMaxDynamicSharedMemorySize,
                         GEMM_SMEM_BYTES);
    cudaFuncSetAttribute(gemm_out_kernel, cudaFuncAttributeMaxDynamicSharedMemorySize,
                         GEMM_SMEM_BYTES);
    cudaFuncSetAttribute(attn_f16_kernel, cudaFuncAttributeMaxDynamicSharedMemorySize,
                         ATTN_SMEM_BYTES);

    gemm_qkv_kernel<<<dim3(N / 128, M / 128, 3), blk, GEMM_SMEM_BYTES>>>(
        (const __half*)pq16, (const __half*)pk16, (const __half*)pv16,
        (const __half*)pwq, (const __half*)pwk, (const __half*)pwv,
        bq, bk, bv,
        (__half*)pQh, (__half*)pKh, (__half*)pVh, M, N, K);

    attn_f16_kernel<<<dim3(S_ / 128, H_, B_), blk, ATTN_SMEM_BYTES>>>();

    gemm_out_kernel<<<dim3(N / 128, M / 128), blk, GEMM_SMEM_BYTES>>>(
        (const __half*)pCh, (const __half*)pwo, bo, (float*)d_out, M, N, K);
}

// round 12
// speedup vs baseline: 1.5273x; 1.0312x over previous
#include <cuda_runtime.h>
#include <cuda_fp16.h>
#include <math.h>

#define B_ 2
#define S_ 2048
#define D_ 1024
#define H_ 16
#define DK_ 64
#define NT_ (S_ / 64)
#define LOG2E_ 1.4426950408889634f
#define NORM_LOG2E_ 0.18033688011112042f   // 0.125 * log2(e)

// Scratch (allocation-free rule: device globals)
__device__ __half g_q16[(size_t)B_ * S_ * D_];
__device__ __half g_k16[(size_t)B_ * S_ * D_];
__device__ __half g_v16[(size_t)B_ * S_ * D_];
__device__ __half g_wq16[(size_t)D_ * D_];
__device__ __half g_wk16[(size_t)D_ * D_];
__device__ __half g_wv16[(size_t)D_ * D_];
__device__ __half g_wo16[(size_t)D_ * D_];
__device__ __half g_Qh[(size_t)B_ * S_ * D_];
__device__ __half g_Kh[(size_t)B_ * S_ * D_];
__device__ __half g_Vh[(size_t)B_ * S_ * D_];
__device__ __half g_ctxh[(size_t)B_ * S_ * D_];
// Permuted masks, fragment order, fp16. pm0 holds mask0 * log2(e).
__device__ __half2 g_pm0h[(size_t)B_ * 128 * 32 * 512];
__device__ __half2 g_pm1h[(size_t)B_ * 128 * 32 * 512];

__device__ __forceinline__ void mma_f16(float c[4], const unsigned a[4], const unsigned b0, const unsigned b1) {
    asm volatile(
        "mma.sync.aligned.m16n8k16.row.col.f32.f16.f16.f32 "
        "{%0,%1,%2,%3}, {%4,%5,%6,%7}, {%8,%9}, {%0,%1,%2,%3};"
        : "+f"(c[0]), "+f"(c[1]), "+f"(c[2]), "+f"(c[3])
        : "r"(a[0]), "r"(a[1]), "r"(a[2]), "r"(a[3]), "r"(b0), "r"(b1));
}
__device__ __forceinline__ void ldsm_x4(unsigned d[4], unsigned addr) {
    asm volatile("ldmatrix.sync.aligned.m8n8.x4.shared.b16 {%0,%1,%2,%3}, [%4];"
                 : "=r"(d[0]), "=r"(d[1]), "=r"(d[2]), "=r"(d[3]) : "r"(addr));
}
__device__ __forceinline__ void ldsm_x4_t(unsigned d[4], unsigned addr) {
    asm volatile("ldmatrix.sync.aligned.m8n8.x4.trans.shared.b16 {%0,%1,%2,%3}, [%4];"
                 : "=r"(d[0]), "=r"(d[1]), "=r"(d[2]), "=r"(d[3]) : "r"(addr));
}
__device__ __forceinline__ void cp_async16(unsigned smem_dst, const void* gsrc) {
    asm volatile("cp.async.cg.shared.global [%0], [%1], 16;" :: "r"(smem_dst), "l"(gsrc));
}
__device__ __forceinline__ void cp_commit() { asm volatile("cp.async.commit_group;"); }
__device__ __forceinline__ void cp_wait0()  { asm volatile("cp.async.wait_group 0;"); }
__device__ __forceinline__ void cp_wait1()  { asm volatile("cp.async.wait_group 1;"); }
__device__ __forceinline__ unsigned h2u(__half2 h) { return *(unsigned*)&h; }
__device__ __forceinline__ float ex2f(float x) {
    float r; asm("ex2.approx.ftz.f32 %0, %1;" : "=f"(r) : "f"(x)); return r;
}

// ---------------------------------------------------------------------------
// Fused pre-pass: 7x fp32->fp16 conversion AND mask permute in ONE launch.
// pm0 is pre-scaled by log2(e) so the softmax can use raw ex2.
// ---------------------------------------------------------------------------
__global__ __launch_bounds__(512)
void prepass_kernel(const float* __restrict__ q, const float* __restrict__ k,
                    const float* __restrict__ v, const float* __restrict__ wq,
                    const float* __restrict__ wk, const float* __restrict__ wv,
                    const float* __restrict__ wo,
                    const float* __restrict__ m0, const float* __restrict__ m1,
                    __half* dq, __half* dk, __half* dv,
                    __half* dwq, __half* dwk, __half* dwv, __half* dwo,
                    __half2* pm0, __half2* pm1)
{
    const int bx = blockIdx.x;
    const int tid = threadIdx.x;
    if (bx < 4096) {
        const float* src; __half* dst; int base;
        if      (bx < 1024) { src = q;  dst = dq;  base = bx; }
        else if (bx < 2048) { src = k;  dst = dk;  base = bx - 1024; }
        else if (bx < 3072) { src = v;  dst = dv;  base = bx - 2048; }
        else if (bx < 3328) { src = wq; dst = dwq; base = bx - 3072; }
        else if (bx < 3584) { src = wk; dst = dwk; base = bx - 3328; }
        else if (bx < 3840) { src = wv; dst = dwv; base = bx - 3584; }
        else                { src = wo; dst = dwo; base = bx - 3840; }
        int i = (base * 512 + tid) * 8;
        float4 a = *(const float4*)&src[i];
        float4 b = *(const float4*)&src[i + 4];
        uint4 o;
        o.x = h2u(__floats2half2_rn(a.x, a.y));
        o.y = h2u(__floats2half2_rn(a.z, a.w));
        o.z = h2u(__floats2half2_rn(b.x, b.y));
        o.w = h2u(__floats2half2_rn(b.z, b.w));
        *(uint4*)&dst[i] = o;
    } else {
        const int pbx = bx - 4096;
        const int kt = pbx & 31;
        const int wt = (pbx >> 5) & 127;
        const int b = pbx >> 12;
        const int c = tid >> 5, l = tid & 31;
        const int rq = l >> 2, cq = l & 3;
        const int row = wt * 16 + rq + ((c >= 8) ? 8 : 0);
        const int col = kt * 64 + (c & 7) * 8 + cq * 2;
        const size_t soff = ((size_t)b * S_ + row) * S_ + col;
        const size_t doff = (((size_t)(b * 128 + wt)) * 32 + kt) * 512 + c * 32 + l;
        float2 a = *(const float2*)&m0[soff];
        float2 bb = *(const float2*)&m1[soff];
        pm0[doff] = __floats2half2_rn(a.x * LOG2E_, a.y * LOG2E_);
        pm1[doff] = __floats2half2_rn(bb.x, bb.y);
    }
}

// ---------------------------------------------------------------------------
// fp16 GEMM core, cp.async 3-stage, K-tile 64, one syncthreads per iter.
// (unchanged from R11, known-good)
// ---------------------------------------------------------------------------
#define GSTG_ (128 * 72)
#define GEMM_SMEM_BYTES (6 * GSTG_ * 2)

__device__ __forceinline__
void gemm_fill(unsigned as_u, unsigned bs_u, int s,
               const __half* __restrict__ A, const __half* __restrict__ W,
               int m0, int n0, int K, int kc, int tid)
{
    const unsigned off = (unsigned)(s * GSTG_ * 2);
    const int srow = tid >> 3;
    const int sc8 = (tid & 7) << 3;
#pragma unroll
    for (int i = 0; i < 4; i++) {
        int row = srow + i * 32;
        cp_async16(as_u + off + (row * 72 + sc8) * 2, A + (size_t)(m0 + row) * K + kc * 64 + sc8);
        cp_async16(bs_u + off + (row * 72 + sc8) * 2, W + (size_t)(n0 + row) * K + kc * 64 + sc8);
    }
}

__device__ __forceinline__
void gemm_core(const __half* __restrict__ A, const __half* __restrict__ W,
               const float* __restrict__ bias, void* __restrict__ Cout,
               int M, int N, int K, int half_out, __half* gsm)
{
    __half* As = gsm;
    __half* Bs = gsm + 3 * GSTG_;

    const int tid = threadIdx.x;
    const int lane = tid & 31;
    const int wid = tid >> 5;
    const int mbase = (wid & 3) << 5;
    const int nbase = (wid >> 2) << 6;
    const int m0 = blockIdx.y << 7;
    const int n0 = blockIdx.x << 7;

    const unsigned as_u = (unsigned)__cvta_generic_to_shared(As);
    const unsigned bs_u = (unsigned)__cvta_generic_to_shared(Bs);
    const unsigned a_loff = ((((lane >> 3) & 1) * 8 + (lane & 7)) * 72 + ((lane >> 4) & 1) * 8) * 2;
    const unsigned b_loff = ((((lane >> 4) & 1) * 8 + (lane & 7)) * 72 + ((lane >> 3) & 1) * 8) * 2;

    float acc[2][8][4] = {};
    const int NK = K / 64;

    gemm_fill(as_u, bs_u, 0, A, W, m0, n0, K, 0, tid); cp_commit();
    gemm_fill(as_u, bs_u, 1, A, W, m0, n0, K, 1, tid); cp_commit();

    for (int kk = 0; kk < NK; kk++) {
        const int buf = kk % 3;
        cp_wait1();
        __syncthreads();
        if (kk + 2 < NK)
            gemm_fill(as_u, bs_u, (kk + 2) % 3, A, W, m0, n0, K, kk + 2, tid);
        cp_commit();

        const unsigned abase = as_u + (unsigned)(buf * GSTG_ * 2);
        const unsigned bbase = bs_u + (unsigned)(buf * GSTG_ * 2);
#pragma unroll
        for (int t = 0; t < 4; t++) {
            unsigned af[2][4];
#pragma unroll
            for (int mt = 0; mt < 2; mt++)
                ldsm_x4(af[mt], abase + ((mbase + (mt << 4)) * 72 + (t << 4)) * 2 + a_loff);
#pragma unroll
            for (int a = 0; a < 8; a += 2) {
                unsigned bf[4];
                ldsm_x4(bf, bbase + ((nbase + (a << 3)) * 72 + (t << 4)) * 2 + b_loff);
                mma_f16(acc[0][a],     af[0], bf[0], bf[1]);
                mma_f16(acc[0][a + 1], af[0], bf[2], bf[3]);
                mma_f16(acc[1][a],     af[1], bf[0], bf[1]);
                mma_f16(acc[1][a + 1], af[1], bf[2], bf[3]);
            }
        }
    }

    const int rq = lane >> 2, cq = lane & 3;
#pragma unroll
    for (int mt = 0; mt < 2; mt++) {
#pragma unroll
        for (int nt = 0; nt < 8; nt++) {
            int r = m0 + mbase + (mt << 4) + rq;
            int c = n0 + nbase + (nt << 3) + (cq << 1);
            float b0 = bias[c], b1 = bias[c + 1];
            float v00 = acc[mt][nt][0] + b0, v01 = acc[mt][nt][1] + b1;
            float v10 = acc[mt][nt][2] + b0, v11 = acc[mt][nt][3] + b1;
            if (half_out) {
                __half* Ch = (__half*)Cout;
                *(__half2*)&Ch[(size_t)r * N + c]       = __floats2half2_rn(v00, v01);
                *(__half2*)&Ch[(size_t)(r + 8) * N + c] = __floats2half2_rn(v10, v11);
            } else {
                float* Cf = (float*)Cout;
                *(float2*)&Cf[(size_t)r * N + c]       = make_float2(v00, v01);
                *(float2*)&Cf[(size_t)(r + 8) * N + c] = make_float2(v10, v11);
            }
        }
    }
}

__global__ __launch_bounds__(256, 2)
void gemm_qkv_kernel(const __half* __restrict__ aq, const __half* __restrict__ ak,
                     const __half* __restrict__ av,
                     const __half* __restrict__ wq, const __half* __restrict__ wk,
                     const __half* __restrict__ wv,
                     const float* __restrict__ bq, const float* __restrict__ bk,
                     const float* __restrict__ bv,
                     __half* oq, __half* ok, __half* ov, int M, int N, int K)
{
    extern __shared__ __half gsm[];
    const int z = blockIdx.z;
    const __half* A = (z == 0) ? aq : (z == 1) ? ak : av;
    const __half* W = (z == 0) ? wq : (z == 1) ? wk : wv;
    const float* bias = (z == 0) ? bq : (z == 1) ? bk : bv;
    __half* O = (z == 0) ? oq : (z == 1) ? ok : ov;
    gemm_core(A, W, bias, O, M, N, K, 1, gsm);
}

__global__ __launch_bounds__(256, 2)
void gemm_out_kernel(const __half* __restrict__ A, const __half* __restrict__ W,
                     const float* __restrict__ bias, float* __restrict__ C,
                     int M, int N, int K)
{
    extern __shared__ __half gsm[];
    gemm_core(A, W, bias, C, M, N, K, 0, gsm);
}

// ---------------------------------------------------------------------------
// fp16 flash attention: R7 math, 3-stage KV pipeline, ex2-based softmax.
// ---------------------------------------------------------------------------
#define Q_WORDS_ (128 * 72)
#define KV_WORDS_ (64 * 72)
#define ATTN_SMEM_BYTES ((Q_WORDS_ + 6 * KV_WORDS_) * 2)

__global__ __launch_bounds__(256, 2)
void attn_f16_kernel()
{
    extern __shared__ __half smh[];
    __half* Qs = smh;

    const int tid = threadIdx.x;
    const int lane = tid & 31;
    const int wid = tid >> 5;
    const int wm = wid << 4;
    const int rq = lane >> 2, cq = lane & 3;
    const int q0 = blockIdx.x << 7;
    const int h = blockIdx.y, b = blockIdx.z;
    const size_t base = ((size_t)(b * H_ + h) * S_) * DK_;
    const __half* Qg = g_Qh + base;
    const __half* Kg = g_Kh + base;
    const __half* Vg = g_Vh + base;

    const size_t wt = (size_t)(b * 128 + (q0 >> 4) + wid);
    const __half2* pm0 = g_pm0h + wt * 32 * 512 + lane;
    const __half2* pm1 = g_pm1h + wt * 32 * 512 + lane;

    unsigned ku[3], vu[3];
    {
        unsigned kv0 = (unsigned)__cvta_generic_to_shared(smh + Q_WORDS_);
#pragma unroll
        for (int s = 0; s < 3; s++) {
            ku[s] = kv0 + (unsigned)(s * KV_WORDS_ * 2);
            vu[s] = kv0 + (unsigned)((3 + s) * KV_WORDS_ * 2);
        }
    }

    const unsigned k_loff = ((((lane >> 4) & 1) * 8 + (lane & 7)) * 72 + ((lane >> 3) & 1) * 8) * 2;
    const unsigned v_loff = ((((lane >> 3) & 1) * 8 + (lane & 7)) * 72 + ((lane >> 4) & 1) * 8) * 2;

    const int srow0 = tid >> 3, sc8 = (tid & 7) << 3;
    const int srow1 = srow0 + 32;

    // prologue: stage KV tiles 0 and 1 (two groups)
#pragma unroll
    for (int s = 0; s < 2; s++) {
        const __half* Kt = Kg + (size_t)(s << 6) * 64;
        const __half* Vt = Vg + (size_t)(s << 6) * 64;
        cp_async16(ku[s] + (srow0 * 72 + sc8) * 2, Kt + srow0 * 64 + sc8);
        cp_async16(ku[s] + (srow1 * 72 + sc8) * 2, Kt + srow1 * 64 + sc8);
        cp_async16(vu[s] + (srow0 * 72 + sc8) * 2, Vt + srow0 * 64 + sc8);
        cp_async16(vu[s] + (srow1 * 72 + sc8) * 2, Vt + srow1 * 64 + sc8);
        cp_commit();
    }

    // stage Q
#pragma unroll
    for (int i = 0; i < 4; i++) {
        int flat = tid + (i << 8);
        int row = flat >> 3, c8 = (flat & 7) << 3;
        *(uint4*)&Qs[row * 72 + c8] = *(const uint4*)&Qg[(size_t)(q0 + row) * 64 + c8];
    }
    __syncthreads();   // Q visible to all warps

    unsigned qf[4][4];
#pragma unroll
    for (int t = 0; t < 4; t++) {
        const __half* qr = &Qs[(wm + rq) * 72 + (t << 4) + (cq << 1)];
        qf[t][0] = *(const unsigned*)qr;
        qf[t][1] = *(const unsigned*)(qr + 8 * 72);
        qf[t][2] = *(const unsigned*)(qr + 8);
        qf[t][3] = *(const unsigned*)(qr + 8 * 72 + 8);
    }

    float Z0 = 0.0f, Z1 = 0.0f;
    float oacc[8][4] = {};

    for (int kt = 0; kt < NT_; kt++) {
        const int cur = kt % 3;

        cp_wait1();          // this tile's KV group complete
        __syncthreads();     // cross-thread visibility; prior compute done
        if (kt + 2 < NT_) {
            const int nb = (kt + 2) % 3;
            const __half* Kn = Kg + (size_t)((kt + 2) << 6) * 64;
            const __half* Vn = Vg + (size_t)((kt + 2) << 6) * 64;
            cp_async16(ku[nb] + (srow0 * 72 + sc8) * 2, Kn + srow0 * 64 + sc8);
            cp_async16(ku[nb] + (srow1 * 72 + sc8) * 2, Kn + srow1 * 64 + sc8);
            cp_async16(vu[nb] + (srow0 * 72 + sc8) * 2, Vn + srow0 * 64 + sc8);
            cp_async16(vu[nb] + (srow1 * 72 + sc8) * 2, Vn + srow1 * 64 + sc8);
        }
        cp_commit();

        // S = Q @ K^T
        float sacc[8][4] = {};
#pragma unroll
        for (int t = 0; t < 4; t++) {
#pragma unroll
            for (int a = 0; a < 8; a += 2) {
                unsigned bf[4];
                ldsm_x4(bf, ku[cur] + ((a << 3) * 72 + (t << 4)) * 2 + k_loff);
                mma_f16(sacc[a],     qf[t], bf[0], bf[1]);
                mma_f16(sacc[a + 1], qf[t], bf[2], bf[3]);
            }
        }

        // Unshifted softmax via ex2: e = 2^(s*NORM*log2e + m0*log2e)
        const __half2* p0 = pm0 + kt * 512;
        const __half2* p1 = pm1 + kt * 512;
        unsigned pf[4][4];
#pragma unroll
        for (int t = 0; t < 4; t++) {
#pragma unroll
            for (int s = 0; s < 2; s++) {
                int nt = (t << 1) + s;
                float2 ma  = __half22float2(p0[nt << 5]);
                float2 mb  = __half22float2(p0[(nt + 8) << 5]);
                float2 m1a = __half22float2(p1[nt << 5]);
                float2 m1b = __half22float2(p1[(nt + 8) << 5]);
                float e0 = ex2f(fmaf(sacc[nt][0], NORM_LOG2E_, ma.x));
                float e1 = ex2f(fmaf(sacc[nt][1], NORM_LOG2E_, ma.y));
                float e2 = ex2f(fmaf(sacc[nt][2], NORM_LOG2E_, mb.x));
                float e3 = ex2f(fmaf(sacc[nt][3], NORM_LOG2E_, mb.y));
                Z0 += e0 + e1;
                Z1 += e2 + e3;
                pf[t][0 + s * 2] = h2u(__floats2half2_rn(e0 * m1a.x, e1 * m1a.y));
                pf[t][1 + s * 2] = h2u(__floats2half2_rn(e2 * m1b.x, e3 * m1b.y));
            }
        }

        // O += P @ V
#pragma unroll
        for (int t = 0; t < 4; t++) {
#pragma unroll
            for (int u = 0; u < 4; u++) {
                unsigned bf[4];
                ldsm_x4_t(bf, vu[cur] + ((t << 4) * 72 + (u << 4)) * 2 + v_loff);
                mma_f16(oacc[(u << 1)],     pf[t], bf[0], bf[1]);
                mma_f16(oacc[(u << 1) + 1], pf[t], bf[2], bf[3]);
            }
        }
    }

    Z0 += __shfl_xor_sync(0xffffffffu, Z0, 1);
    Z0 += __shfl_xor_sync(0xffffffffu, Z0, 2);
    Z1 += __shfl_xor_sync(0xffffffffu, Z1, 1);
    Z1 += __shfl_xor_sync(0xffffffffu, Z1, 2);
    float i0 = 1.0f / Z0, i1 = 1.0f / Z1;

    __half* Og = g_ctxh + base;
#pragma unroll
    for (int nt = 0; nt < 8; nt++) {
        int col = (nt << 3) + (cq << 1);
        *(__half2*)&Og[(size_t)(q0 + wm + rq) * 64 + col] =
            __floats2half2_rn(oacc[nt][0] * i0, oacc[nt][1] * i0);
        *(__half2*)&Og[(size_t)(q0 + wm + rq + 8) * 64 + col] =
            __floats2half2_rn(oacc[nt][2] * i1, oacc[nt][3] * i1);
    }
}

extern "C" void kernel_launch(void* const* d_in, const int* in_sizes, int n_in,
                              void* d_out, int out_size)
{
    const float* q  = (const float*)d_in[0];
    const float* k  = (const float*)d_in[1];
    const float* v  = (const float*)d_in[2];
    const float* m0 = (const float*)d_in[3];
    const float* m1 = (const float*)d_in[4];
    const float* wq = (const float*)d_in[5];
    const float* bq = (const float*)d_in[6];
    const float* wk = (const float*)d_in[7];
    const float* bk = (const float*)d_in[8];
    const float* wv = (const float*)d_in[9];
    const float* bv = (const float*)d_in[10];
    const float* wo = (const float*)d_in[11];
    const float* bo = (const float*)d_in[12];

    void *pq16, *pk16, *pv16, *pwq, *pwk, *pwv, *pwo;
    void *pQh, *pKh, *pVh, *pCh, *ppm0, *ppm1;
    cudaGetSymbolAddress(&pq16, g_q16);
    cudaGetSymbolAddress(&pk16, g_k16);
    cudaGetSymbolAddress(&pv16, g_v16);
    cudaGetSymbolAddress(&pwq, g_wq16);
    cudaGetSymbolAddress(&pwk, g_wk16);
    cudaGetSymbolAddress(&pwv, g_wv16);
    cudaGetSymbolAddress(&pwo, g_wo16);
    cudaGetSymbolAddress(&pQh, g_Qh);
    cudaGetSymbolAddress(&pKh, g_Kh);
    cudaGetSymbolAddress(&pVh, g_Vh);
    cudaGetSymbolAddress(&pCh, g_ctxh);
    cudaGetSymbolAddress(&ppm0, g_pm0h);
    cudaGetSymbolAddress(&ppm1, g_pm1h);

    const int M = B_ * S_, N = D_, K = D_;

    prepass_kernel<<<12288, 512>>>(q, k, v, wq, wk, wv, wo, m0, m1,
                                   (__half*)pq16, (__half*)pk16, (__half*)pv16,
                                   (__half*)pwq, (__half*)pwk, (__half*)pwv, (__half*)pwo,
                                   (__half2*)ppm0, (__half2*)ppm1);

    dim3 blk(256);
    cudaFuncSetAttribute(gemm_qkv_kernel, cudaFuncAttributeMaxDynamicSharedMemorySize,
                         GEMM_SMEM_BYTES);
    cudaFuncSetAttribute(gemm_out_kernel, cudaFuncAttributeMaxDynamicSharedMemorySize,
                         GEMM_SMEM_BYTES);
    cudaFuncSetAttribute(attn_f16_kernel, cudaFuncAttributeMaxDynamicSharedMemorySize,
                         ATTN_SMEM_BYTES);

    gemm_qkv_kernel<<<dim3(N / 128, M / 128, 3), blk, GEMM_SMEM_BYTES>>>(
        (const __half*)pq16, (const __half*)pk16, (const __half*)pv16,
        (const __half*)pwq, (const __half*)pwk, (const __half*)pwv,
        bq, bk, bv,
        (__half*)pQh, (__half*)pKh, (__half*)pVh, M, N, K);

    attn_f16_kernel<<<dim3(S_ / 128, H_, B_), blk, ATTN_SMEM_BYTES>>>();

    gemm_out_kernel<<<dim3(N / 128, M / 128), blk, GEMM_SMEM_BYTES>>>(
        (const __half*)pCh, (const __half*)pwo, bo, (float*)d_out, M, N, K);
}